// round 1
// baseline (speedup 1.0000x reference)
#include <cuda_runtime.h>
#include <cmath>

// Problem constants
#define I_DIM 512
#define H_DIM 512
#define KTOT  1024   // I_DIM + H_DIM
#define NTOT  1024   // 512 tau logits + 512 f pre-activations

// Scratch (allocation-free rule: __device__ globals)
__device__ float g_C[(size_t)65536 * NTOT];   // GEMM output [B, 1024]
__device__ float g_Bt[(size_t)KTOT * NTOT];   // packed weights, k-major: Bt[k*1024 + n]

// ---------------------------------------------------------------------------
// Pack combined weight matrix, transposed to k-major for coalesced GEMM loads.
// Output column n (of C):
//   n <  512 : tau logits -> W_tau[n, k]              (W_tau is [512, 1024])
//   n >= 512 : f pre      -> k<512 ? W_in[n-512, k] : W_rec[n-512, k-512]
// ---------------------------------------------------------------------------
__global__ void pack_bt_kernel(const float* __restrict__ W_in,
                               const float* __restrict__ W_rec,
                               const float* __restrict__ W_tau,
                               float* __restrict__ Bt) {
    int idx = blockIdx.x * blockDim.x + threadIdx.x;   // over 1024*1024
    int k = idx >> 10;
    int n = idx & 1023;
    float v;
    if (n < H_DIM) {
        v = W_tau[n * KTOT + k];
    } else {
        int m = n - H_DIM;
        v = (k < I_DIM) ? W_in[m * I_DIM + k] : W_rec[m * H_DIM + (k - I_DIM)];
    }
    Bt[idx] = v;
}

// ---------------------------------------------------------------------------
// SGEMM: C[B,1024] = A[B,1024] @ B[1024,1024]^T, where A = [x | h] (virtual).
// BM=128, BN=128, BK=16, 256 threads, 8x8 register tile per thread.
// ---------------------------------------------------------------------------
#define BM 128
#define BN 128
#define BK 16

__global__ __launch_bounds__(256, 2)
void gemm_kernel(const float* __restrict__ x, const float* __restrict__ h,
                 const float* __restrict__ Bt, float* __restrict__ C) {
    __shared__ float As[BK][BM];
    __shared__ float Bs[BK][BN];

    const int bn = blockIdx.x;           // 8 tiles of columns
    const int bm = blockIdx.y;           // B/128 tiles of rows
    const int tid = threadIdx.x;
    const int tx = tid & 15;             // 16 cols of threads
    const int ty = tid >> 4;             // 16 rows of threads

    const int row0 = bm * BM;
    const int col0 = bn * BN;

    float acc[8][8];
#pragma unroll
    for (int i = 0; i < 8; i++)
#pragma unroll
        for (int j = 0; j < 8; j++) acc[i][j] = 0.f;

    // A-load indexing: 128 rows x 16 k = 2048 floats; 256 threads * 8 floats (2x float4)
    const int a_r  = tid >> 2;           // 0..63
    const int a_k4 = (tid & 3) * 4;      // 0,4,8,12
    // B-load indexing: 16 k x 128 n
    const int b_k  = tid >> 5;           // 0..7
    const int b_n4 = (tid & 31) * 4;     // 0..124

    for (int k0 = 0; k0 < KTOT; k0 += BK) {
        // A source: first 512 k from x, next 512 from h (BK=16 never straddles)
        const float* Asrc = (k0 < I_DIM) ? (x + k0) : (h + (k0 - I_DIM));
#pragma unroll
        for (int i = 0; i < 2; i++) {
            int r = a_r + i * 64;
            float4 v = *(const float4*)(Asrc + (size_t)(row0 + r) * I_DIM + a_k4);
            As[a_k4 + 0][r] = v.x;
            As[a_k4 + 1][r] = v.y;
            As[a_k4 + 2][r] = v.z;
            As[a_k4 + 3][r] = v.w;
        }
#pragma unroll
        for (int i = 0; i < 2; i++) {
            int kk = b_k + i * 8;
            float4 v = *(const float4*)(Bt + (size_t)(k0 + kk) * NTOT + col0 + b_n4);
            *(float4*)&Bs[kk][b_n4] = v;
        }
        __syncthreads();

#pragma unroll
        for (int kk = 0; kk < BK; kk++) {
            float a[8], b[8];
            *(float4*)&a[0] = *(const float4*)&As[kk][ty * 8 + 0];
            *(float4*)&a[4] = *(const float4*)&As[kk][ty * 8 + 4];
            *(float4*)&b[0] = *(const float4*)&Bs[kk][tx * 8 + 0];
            *(float4*)&b[4] = *(const float4*)&Bs[kk][tx * 8 + 4];
#pragma unroll
            for (int i = 0; i < 8; i++)
#pragma unroll
                for (int j = 0; j < 8; j++)
                    acc[i][j] = fmaf(a[i], b[j], acc[i][j]);
        }
        __syncthreads();
    }

#pragma unroll
    for (int i = 0; i < 8; i++) {
        int r = row0 + ty * 8 + i;
        float4* cp = (float4*)(C + (size_t)r * NTOT + col0 + tx * 8);
        cp[0] = make_float4(acc[i][0], acc[i][1], acc[i][2], acc[i][3]);
        cp[1] = make_float4(acc[i][4], acc[i][5], acc[i][6], acc[i][7]);
    }
}

// ---------------------------------------------------------------------------
// Epilogue: per row, tau = 0.5 + 4.5*sigmoid(c_tau + b_tau)
//           f   = tanh(c_f + b_in)
//           y   = h + 0.1*(f - h)/tau
//           new_h = LayerNorm(y)*gamma + beta ; outputs new_h then tau.
// One block per row, 256 threads, 2 elements/thread.
// ---------------------------------------------------------------------------
__global__ __launch_bounds__(256)
void epilogue_kernel(const float* __restrict__ C, const float* __restrict__ h,
                     const float* __restrict__ b_in, const float* __restrict__ b_tau,
                     const float* __restrict__ gamma, const float* __restrict__ beta,
                     float* __restrict__ out_h, float* __restrict__ out_tau) {
    const int row = blockIdx.x;
    const int tid = threadIdx.x;
    const float* crow = C + (size_t)row * NTOT;
    const float* hrow = h + (size_t)row * H_DIM;

    float y[2], tauv[2];
    float s = 0.f, s2 = 0.f;
#pragma unroll
    for (int i = 0; i < 2; i++) {
        int j = tid + i * 256;
        float tl = crow[j] + b_tau[j];
        float sig = 1.0f / (1.0f + __expf(-tl));
        float tau = 0.5f + 4.5f * sig;
        float f = tanhf(crow[H_DIM + j] + b_in[j]);
        float hv = hrow[j];
        float yv = hv + 0.1f * (f - hv) / tau;
        y[i] = yv; tauv[i] = tau;
        s += yv; s2 += yv * yv;
    }

    // block reduce (8 warps)
    __shared__ float red[16];
#pragma unroll
    for (int off = 16; off > 0; off >>= 1) {
        s  += __shfl_xor_sync(0xffffffffu, s, off);
        s2 += __shfl_xor_sync(0xffffffffu, s2, off);
    }
    int warp = tid >> 5, lane = tid & 31;
    if (lane == 0) { red[warp] = s; red[8 + warp] = s2; }
    __syncthreads();
    if (warp == 0) {
        float a = (lane < 8) ? red[lane] : 0.f;
        float b = (lane < 8) ? red[8 + lane] : 0.f;
#pragma unroll
        for (int off = 4; off > 0; off >>= 1) {
            a += __shfl_xor_sync(0xffffffffu, a, off);
            b += __shfl_xor_sync(0xffffffffu, b, off);
        }
        if (lane == 0) { red[0] = a; red[1] = b; }
    }
    __syncthreads();
    float mu  = red[0] * (1.0f / H_DIM);
    float var = red[1] * (1.0f / H_DIM) - mu * mu;
    float inv = rsqrtf(var + 1e-5f);

#pragma unroll
    for (int i = 0; i < 2; i++) {
        int j = tid + i * 256;
        out_h[(size_t)row * H_DIM + j] = (y[i] - mu) * inv * gamma[j] + beta[j];
        out_tau[(size_t)row * H_DIM + j] = tauv[i];
    }
}

// ---------------------------------------------------------------------------
extern "C" void kernel_launch(void* const* d_in, const int* in_sizes, int n_in,
                              void* d_out, int out_size) {
    const float* x     = (const float*)d_in[0];
    const float* h     = (const float*)d_in[1];
    const float* W_in  = (const float*)d_in[2];
    const float* b_in  = (const float*)d_in[3];
    const float* W_rec = (const float*)d_in[4];
    const float* W_tau = (const float*)d_in[5];
    const float* b_tau = (const float*)d_in[6];
    const float* gamma = (const float*)d_in[7];
    const float* beta  = (const float*)d_in[8];

    const int B = in_sizes[0] / I_DIM;   // 65536

    float* out = (float*)d_out;
    float* out_h   = out;                          // new_h: [B, 512]
    float* out_tau = out + (size_t)B * H_DIM;      // tau:   [B, 512]

    float* C  = nullptr;
    float* Bt = nullptr;
    cudaGetSymbolAddress((void**)&C, g_C);
    cudaGetSymbolAddress((void**)&Bt, g_Bt);

    pack_bt_kernel<<<(KTOT * NTOT) / 1024, 1024>>>(W_in, W_rec, W_tau, Bt);

    dim3 ggrid(NTOT / BN, B / BM);
    gemm_kernel<<<ggrid, 256>>>(x, h, Bt, C);

    epilogue_kernel<<<B, 256>>>(C, h, b_in, b_tau, gamma, beta, out_h, out_tau);
}

// round 3
// speedup vs baseline: 2.8573x; 2.8573x over previous
#include <cuda_runtime.h>
#include <cuda_bf16.h>
#include <cstdint>
#include <cmath>

#define I_DIM 512
#define H_DIM 512
#define KTOT  1024
#define NTOT  1024
#define BATCH 65536

// ---------------------------------------------------------------------------
// Device scratch (allocation-free rule)
// ---------------------------------------------------------------------------
// A2: fragment-linear layout: u4 index = ((rb*64 + kb)*2 + term)*32 + lane
//     rb = row-block of 16 (0..4095), kb = k-block of 16 (0..63), term 0=hi 1=lo
__device__ uint4 g_A2[(size_t)4096 * 64 * 2 * 32];   // 256 MB
// W2: u4 index = ((nb*64 + kb)*2 + term)*32 + lane ; nb = n-block of 16 (0..63)
__device__ uint4 g_W2[(size_t)64 * 64 * 2 * 32];     // 4 MB
__device__ float g_C[(size_t)BATCH * NTOT];          // 256 MB

// ---------------------------------------------------------------------------
__device__ __forceinline__ uint32_t smem_u32(const void* p) {
    uint32_t a;
    asm("{ .reg .u64 t; cvta.to.shared.u64 t, %1; cvt.u32.u64 %0, t; }"
        : "=r"(a) : "l"(p));
    return a;
}
__device__ __forceinline__ uint32_t pack_bf2(float a, float b) {
    __nv_bfloat16 ha = __float2bfloat16(a);
    __nv_bfloat16 hb = __float2bfloat16(b);
    return (uint32_t)__bfloat16_as_ushort(ha) |
           ((uint32_t)__bfloat16_as_ushort(hb) << 16);
}
__device__ __forceinline__ float bf_hi(float v) {
    return __bfloat162float(__float2bfloat16(v));
}

__device__ __forceinline__ void mma16816(float* c, const uint4& a,
                                         uint32_t b0, uint32_t b1) {
    asm volatile(
        "mma.sync.aligned.m16n8k16.row.col.f32.bf16.bf16.f32 "
        "{%0,%1,%2,%3}, {%4,%5,%6,%7}, {%8,%9}, {%0,%1,%2,%3};"
        : "+f"(c[0]), "+f"(c[1]), "+f"(c[2]), "+f"(c[3])
        : "r"(a.x), "r"(a.y), "r"(a.z), "r"(a.w), "r"(b0), "r"(b1));
}

#define CP_ASYNC16(dst, src) \
    asm volatile("cp.async.cg.shared.global [%0], [%1], 16;" \
                 :: "r"(dst), "l"(src) : "memory")
#define CP_COMMIT() asm volatile("cp.async.commit_group;" ::: "memory")
#define CP_WAIT1()  asm volatile("cp.async.wait_group 1;" ::: "memory")

// ---------------------------------------------------------------------------
// Pack W into fragment-linear hi/lo bf16 tiles.
// Combined weight: n<512 -> W_tau[n][k]; else k<512 ? W_in[n-512][k]
//                                              : W_rec[n-512][k-512]
// ---------------------------------------------------------------------------
__device__ __forceinline__ float w_at(const float* W_in, const float* W_rec,
                                      const float* W_tau, int n, int k) {
    if (n < H_DIM) return W_tau[n * KTOT + k];
    int m = n - H_DIM;
    return (k < I_DIM) ? W_in[m * I_DIM + k] : W_rec[m * H_DIM + (k - I_DIM)];
}

__global__ void pack_w_kernel(const float* __restrict__ W_in,
                              const float* __restrict__ W_rec,
                              const float* __restrict__ W_tau) {
    int t = blockIdx.x * blockDim.x + threadIdx.x;  // 131072 threads
    int lane = t & 31;
    int idx = t >> 5;
    int kb = idx & 63;
    int nb = idx >> 6;

    int n0 = nb * 16 + (lane >> 2);
    int k0 = kb * 16 + (lane & 3) * 2;

    float v[8];
    v[0] = w_at(W_in, W_rec, W_tau, n0,     k0);
    v[1] = w_at(W_in, W_rec, W_tau, n0,     k0 + 1);
    v[2] = w_at(W_in, W_rec, W_tau, n0,     k0 + 8);
    v[3] = w_at(W_in, W_rec, W_tau, n0,     k0 + 9);
    v[4] = w_at(W_in, W_rec, W_tau, n0 + 8, k0);
    v[5] = w_at(W_in, W_rec, W_tau, n0 + 8, k0 + 1);
    v[6] = w_at(W_in, W_rec, W_tau, n0 + 8, k0 + 8);
    v[7] = w_at(W_in, W_rec, W_tau, n0 + 8, k0 + 9);

    uint4 hi, lo;
    hi.x = pack_bf2(v[0], v[1]); hi.y = pack_bf2(v[2], v[3]);
    hi.z = pack_bf2(v[4], v[5]); hi.w = pack_bf2(v[6], v[7]);
    lo.x = pack_bf2(v[0] - bf_hi(v[0]), v[1] - bf_hi(v[1]));
    lo.y = pack_bf2(v[2] - bf_hi(v[2]), v[3] - bf_hi(v[3]));
    lo.z = pack_bf2(v[4] - bf_hi(v[4]), v[5] - bf_hi(v[5]));
    lo.w = pack_bf2(v[6] - bf_hi(v[6]), v[7] - bf_hi(v[7]));

    size_t base = ((size_t)(nb * 64 + kb) * 2) * 32 + lane;
    g_W2[base]      = hi;
    g_W2[base + 32] = lo;
}

// ---------------------------------------------------------------------------
// Split A = [x | h] into fragment-linear hi/lo bf16 tiles.
// One block per 16-row block; 8 warps x 8 kb each.
// ---------------------------------------------------------------------------
__global__ __launch_bounds__(256)
void split_a_kernel(const float* __restrict__ x, const float* __restrict__ h) {
    const int rb = blockIdx.x;            // 0..4095
    const int tid = threadIdx.x;
    const int wid = tid >> 5;
    const int lane = tid & 31;

    const int r0 = lane >> 2;
    const int cq = (lane & 3) * 2;
    const size_t rowA = (size_t)rb * 16 + r0;
    const size_t rowB = rowA + 8;

#pragma unroll
    for (int j = 0; j < 8; j++) {
        int kb = wid * 8 + j;             // 0..63
        int kg = kb * 16 + cq;
        const float* srcA;
        const float* srcB;
        if (kb < 32) { srcA = x + rowA * I_DIM + kg;          srcB = x + rowB * I_DIM + kg; }
        else         { srcA = h + rowA * H_DIM + (kg - 512);  srcB = h + rowB * H_DIM + (kg - 512); }

        float a0 = srcA[0], a1 = srcA[1], a2 = srcA[8], a3 = srcA[9];
        float b0 = srcB[0], b1 = srcB[1], b2 = srcB[8], b3 = srcB[9];

        uint4 hi, lo;
        hi.x = pack_bf2(a0, a1); hi.y = pack_bf2(b0, b1);
        hi.z = pack_bf2(a2, a3); hi.w = pack_bf2(b2, b3);
        lo.x = pack_bf2(a0 - bf_hi(a0), a1 - bf_hi(a1));
        lo.y = pack_bf2(b0 - bf_hi(b0), b1 - bf_hi(b1));
        lo.z = pack_bf2(a2 - bf_hi(a2), a3 - bf_hi(a3));
        lo.w = pack_bf2(b2 - bf_hi(b2), b3 - bf_hi(b3));

        size_t base = ((size_t)(rb * 64 + kb) * 2) * 32 + lane;
        g_A2[base]      = hi;
        g_A2[base + 32] = lo;
    }
}

// ---------------------------------------------------------------------------
// GEMM: C[BATCH,1024] = A @ W^T via mma.sync bf16, 3-term split accumulate.
// CTA 128x128, BK=32 (2 k16 blocks), 3-stage cp.async pipeline, 8 warps.
// smem stage (32KB): A chunks [kb][t][mb][lane], then B chunks [kb][t][nb'][lane]
// ---------------------------------------------------------------------------
#define STAGE_BYTES 32768
#define N_STAGES 3

__global__ __launch_bounds__(256)
void gemm_mma_kernel() {
    extern __shared__ char smem[];
    const uint32_t sbase = smem_u32(smem);

    const int tid  = threadIdx.x;
    const int wid  = tid >> 5;
    const int lane = tid & 31;
    const int bn = blockIdx.x;            // 0..7
    const int bm = blockIdx.y;            // 0..511

    // --- per-thread cp.async source offsets (u4 units, at iter 0) + smem dst
    uint32_t soff[8];
    const uint4* gptr[8];
#pragma unroll
    for (int j = 0; j < 8; j++) {
        int c = tid + j * 256;            // chunk id 0..2047
        int cl   = c & 31;
        int blk  = (c >> 5) & 7;          // mb or nb
        int term = (c >> 8) & 1;
        int kb   = (c >> 9) & 1;
        if (c < 1024) {
            int rb = bm * 8 + blk;
            gptr[j] = g_A2 + (((size_t)(rb * 64 + kb) * 2 + term) * 32 + cl);
        } else {
            int nb = bn * 8 + blk;
            gptr[j] = g_W2 + (((size_t)(nb * 64 + kb) * 2 + term) * 32 + cl);
        }
        soff[j] = (uint32_t)(c * 16);     // within stage (A first 16KB, B next)
    }

    float acc[4][4][4];
#pragma unroll
    for (int a = 0; a < 4; a++)
#pragma unroll
        for (int b = 0; b < 4; b++)
#pragma unroll
            for (int d = 0; d < 4; d++) acc[a][b][d] = 0.f;

    // prologue: stages 0,1 (k-iters 0,1). A/W advance 128 u4 per k-iter.
#pragma unroll
    for (int s = 0; s < 2; s++) {
#pragma unroll
        for (int j = 0; j < 8; j++)
            CP_ASYNC16(sbase + s * STAGE_BYTES + soff[j], gptr[j] + (size_t)s * 128);
        CP_COMMIT();
    }

    const int mbB = (wid & 1) * 4;        // warp m-block base (of 8)
    const int nbB = (wid >> 1) * 2;       // warp n-block base (of 8, 16-wide)

    for (int i = 0; i < 32; i++) {
        CP_WAIT1();
        __syncthreads();

        // issue stage i+2
        if (i + 2 < 32) {
            uint32_t sb = sbase + ((i + 2) % N_STAGES) * STAGE_BYTES;
#pragma unroll
            for (int j = 0; j < 8; j++)
                CP_ASYNC16(sb + soff[j], gptr[j] + (size_t)(i + 2) * 128);
        }
        CP_COMMIT();

        const uint32_t st = sbase + (i % N_STAGES) * STAGE_BYTES;
#pragma unroll
        for (int kb = 0; kb < 2; kb++) {
            uint4 ah[4], al[4], bh[2], bl[2];
#pragma unroll
            for (int mb = 0; mb < 4; mb++) {
                uint32_t ahi = st + ((kb * 2 + 0) * 8 + mbB + mb) * 512 + lane * 16;
                uint32_t alo = st + ((kb * 2 + 1) * 8 + mbB + mb) * 512 + lane * 16;
                asm volatile("ld.shared.v4.u32 {%0,%1,%2,%3}, [%4];"
                    : "=r"(ah[mb].x), "=r"(ah[mb].y), "=r"(ah[mb].z), "=r"(ah[mb].w) : "r"(ahi));
                asm volatile("ld.shared.v4.u32 {%0,%1,%2,%3}, [%4];"
                    : "=r"(al[mb].x), "=r"(al[mb].y), "=r"(al[mb].z), "=r"(al[mb].w) : "r"(alo));
            }
#pragma unroll
            for (int p = 0; p < 2; p++) {
                uint32_t bhi = st + 16384 + ((kb * 2 + 0) * 8 + nbB + p) * 512 + lane * 16;
                uint32_t blo = st + 16384 + ((kb * 2 + 1) * 8 + nbB + p) * 512 + lane * 16;
                asm volatile("ld.shared.v4.u32 {%0,%1,%2,%3}, [%4];"
                    : "=r"(bh[p].x), "=r"(bh[p].y), "=r"(bh[p].z), "=r"(bh[p].w) : "r"(bhi));
                asm volatile("ld.shared.v4.u32 {%0,%1,%2,%3}, [%4];"
                    : "=r"(bl[p].x), "=r"(bl[p].y), "=r"(bl[p].z), "=r"(bl[p].w) : "r"(blo));
            }
            // term 0: ah * bh ; term 1: ah * bl ; term 2: al * bh
#pragma unroll
            for (int term = 0; term < 3; term++) {
#pragma unroll
                for (int mt = 0; mt < 4; mt++) {
#pragma unroll
                    for (int nt = 0; nt < 4; nt++) {
                        const uint4& A = (term == 2) ? al[mt] : ah[mt];
                        const uint4& B = (term == 1) ? bl[nt >> 1] : bh[nt >> 1];
                        uint32_t b0 = (nt & 1) ? B.z : B.x;
                        uint32_t b1 = (nt & 1) ? B.w : B.y;
                        mma16816(acc[mt][nt], A, b0, b1);
                    }
                }
            }
        }
        __syncthreads();
    }

    // store C
    const int g  = lane >> 2;
    const int tg = lane & 3;
#pragma unroll
    for (int mt = 0; mt < 4; mt++) {
        int row = bm * 128 + (wid & 1) * 64 + mt * 16 + g;
#pragma unroll
        for (int nt = 0; nt < 4; nt++) {
            int col = bn * 128 + (wid >> 1) * 32 + nt * 8 + tg * 2;
            float2* p0 = (float2*)(g_C + (size_t)row * NTOT + col);
            float2* p1 = (float2*)(g_C + (size_t)(row + 8) * NTOT + col);
            *p0 = make_float2(acc[mt][nt][0], acc[mt][nt][1]);
            *p1 = make_float2(acc[mt][nt][2], acc[mt][nt][3]);
        }
    }
}

// ---------------------------------------------------------------------------
// Epilogue: tau/sigmoid, tanh, Euler step, LayerNorm.
// ---------------------------------------------------------------------------
__global__ __launch_bounds__(256)
void epilogue_kernel(const float* __restrict__ h,
                     const float* __restrict__ b_in, const float* __restrict__ b_tau,
                     const float* __restrict__ gamma, const float* __restrict__ beta,
                     float* __restrict__ out_h, float* __restrict__ out_tau) {
    const int row = blockIdx.x;
    const int tid = threadIdx.x;
    const float* crow = g_C + (size_t)row * NTOT;
    const float* hrow = h + (size_t)row * H_DIM;

    float y[2], tauv[2];
    float s = 0.f, s2 = 0.f;
#pragma unroll
    for (int i = 0; i < 2; i++) {
        int j = tid + i * 256;
        float tl = crow[j] + b_tau[j];
        float sig = 1.0f / (1.0f + __expf(-tl));
        float tau = 0.5f + 4.5f * sig;
        float f = tanhf(crow[H_DIM + j] + b_in[j]);
        float hv = hrow[j];
        float yv = hv + 0.1f * (f - hv) / tau;
        y[i] = yv; tauv[i] = tau;
        s += yv; s2 += yv * yv;
    }

    __shared__ float red[16];
#pragma unroll
    for (int off = 16; off > 0; off >>= 1) {
        s  += __shfl_xor_sync(0xffffffffu, s, off);
        s2 += __shfl_xor_sync(0xffffffffu, s2, off);
    }
    int warp = tid >> 5, lane = tid & 31;
    if (lane == 0) { red[warp] = s; red[8 + warp] = s2; }
    __syncthreads();
    if (warp == 0) {
        float a = (lane < 8) ? red[lane] : 0.f;
        float b = (lane < 8) ? red[8 + lane] : 0.f;
#pragma unroll
        for (int off = 4; off > 0; off >>= 1) {
            a += __shfl_xor_sync(0xffffffffu, a, off);
            b += __shfl_xor_sync(0xffffffffu, b, off);
        }
        if (lane == 0) { red[0] = a; red[1] = b; }
    }
    __syncthreads();
    float mu  = red[0] * (1.0f / H_DIM);
    float var = red[1] * (1.0f / H_DIM) - mu * mu;
    float inv = rsqrtf(var + 1e-5f);

#pragma unroll
    for (int i = 0; i < 2; i++) {
        int j = tid + i * 256;
        out_h[(size_t)row * H_DIM + j] = (y[i] - mu) * inv * gamma[j] + beta[j];
        out_tau[(size_t)row * H_DIM + j] = tauv[i];
    }
}

// ---------------------------------------------------------------------------
extern "C" void kernel_launch(void* const* d_in, const int* in_sizes, int n_in,
                              void* d_out, int out_size) {
    const float* x     = (const float*)d_in[0];
    const float* h     = (const float*)d_in[1];
    const float* W_in  = (const float*)d_in[2];
    const float* b_in  = (const float*)d_in[3];
    const float* W_rec = (const float*)d_in[4];
    const float* W_tau = (const float*)d_in[5];
    const float* b_tau = (const float*)d_in[6];
    const float* gamma = (const float*)d_in[7];
    const float* beta  = (const float*)d_in[8];

    const int B = in_sizes[0] / I_DIM;    // 65536

    float* out = (float*)d_out;
    float* out_h   = out;
    float* out_tau = out + (size_t)B * H_DIM;

    pack_w_kernel<<<512, 256>>>(W_in, W_rec, W_tau);
    split_a_kernel<<<B / 16, 256>>>(x, h);

    cudaFuncSetAttribute(gemm_mma_kernel,
                         cudaFuncAttributeMaxDynamicSharedMemorySize,
                         N_STAGES * STAGE_BYTES);
    dim3 ggrid(NTOT / 128, B / 128);      // (8, 512)
    gemm_mma_kernel<<<ggrid, 256, N_STAGES * STAGE_BYTES>>>();

    epilogue_kernel<<<B, 256>>>(h, b_in, b_tau, gamma, beta, out_h, out_tau);
}

// round 4
// speedup vs baseline: 2.9265x; 1.0242x over previous
#include <cuda_runtime.h>
#include <cuda_bf16.h>
#include <cstdint>
#include <cmath>

#define I_DIM 512
#define H_DIM 512
#define KTOT  1024
#define NTOT  1024
#define BATCH 65536

// ---------------------------------------------------------------------------
// Device scratch
// A2: u4 index = ((rb*64 + kb)*2 + term)*32 + lane   rb: 16-row block, kb: k16 block
// W2: u4 index = ((nb*64 + kb)*2 + term)*32 + lane   nb: 16-col block
// ---------------------------------------------------------------------------
__device__ uint4 g_A2[(size_t)4096 * 64 * 2 * 32];   // 256 MB
__device__ uint4 g_W2[(size_t)64 * 64 * 2 * 32];     // 4 MB
__device__ float g_C[(size_t)BATCH * NTOT];          // 256 MB

__device__ __forceinline__ uint32_t smem_u32(const void* p) {
    uint32_t a;
    asm("{ .reg .u64 t; cvta.to.shared.u64 t, %1; cvt.u32.u64 %0, t; }"
        : "=r"(a) : "l"(p));
    return a;
}
__device__ __forceinline__ uint32_t pack_bf2(float a, float b) {
    __nv_bfloat16 ha = __float2bfloat16(a);
    __nv_bfloat16 hb = __float2bfloat16(b);
    return (uint32_t)__bfloat16_as_ushort(ha) |
           ((uint32_t)__bfloat16_as_ushort(hb) << 16);
}
__device__ __forceinline__ float bf_hi(float v) {
    return __bfloat162float(__float2bfloat16(v));
}
__device__ __forceinline__ void mma16816(float* c, const uint4& a,
                                         uint32_t b0, uint32_t b1) {
    asm volatile(
        "mma.sync.aligned.m16n8k16.row.col.f32.bf16.bf16.f32 "
        "{%0,%1,%2,%3}, {%4,%5,%6,%7}, {%8,%9}, {%0,%1,%2,%3};"
        : "+f"(c[0]), "+f"(c[1]), "+f"(c[2]), "+f"(c[3])
        : "r"(a.x), "r"(a.y), "r"(a.z), "r"(a.w), "r"(b0), "r"(b1));
}
#define CP_ASYNC16(dst, src) \
    asm volatile("cp.async.cg.shared.global [%0], [%1], 16;" \
                 :: "r"(dst), "l"(src) : "memory")
#define CP_COMMIT() asm volatile("cp.async.commit_group;" ::: "memory")
#define CP_WAIT2()  asm volatile("cp.async.wait_group 2;" ::: "memory")
#define LDS128(v, addr) \
    asm volatile("ld.shared.v4.u32 {%0,%1,%2,%3}, [%4];" \
        : "=r"((v).x), "=r"((v).y), "=r"((v).z), "=r"((v).w) : "r"(addr))

// ---------------------------------------------------------------------------
// Pack W into fragment-linear hi/lo bf16 tiles.
// ---------------------------------------------------------------------------
__device__ __forceinline__ float w_at(const float* W_in, const float* W_rec,
                                      const float* W_tau, int n, int k) {
    if (n < H_DIM) return W_tau[n * KTOT + k];
    int m = n - H_DIM;
    return (k < I_DIM) ? W_in[m * I_DIM + k] : W_rec[m * H_DIM + (k - I_DIM)];
}

__global__ void pack_w_kernel(const float* __restrict__ W_in,
                              const float* __restrict__ W_rec,
                              const float* __restrict__ W_tau) {
    int t = blockIdx.x * blockDim.x + threadIdx.x;
    int lane = t & 31;
    int idx = t >> 5;
    int kb = idx & 63;
    int nb = idx >> 6;

    int n0 = nb * 16 + (lane >> 2);
    int k0 = kb * 16 + (lane & 3) * 2;

    float v[8];
    v[0] = w_at(W_in, W_rec, W_tau, n0,     k0);
    v[1] = w_at(W_in, W_rec, W_tau, n0,     k0 + 1);
    v[2] = w_at(W_in, W_rec, W_tau, n0,     k0 + 8);
    v[3] = w_at(W_in, W_rec, W_tau, n0,     k0 + 9);
    v[4] = w_at(W_in, W_rec, W_tau, n0 + 8, k0);
    v[5] = w_at(W_in, W_rec, W_tau, n0 + 8, k0 + 1);
    v[6] = w_at(W_in, W_rec, W_tau, n0 + 8, k0 + 8);
    v[7] = w_at(W_in, W_rec, W_tau, n0 + 8, k0 + 9);

    uint4 hi, lo;
    hi.x = pack_bf2(v[0], v[1]); hi.y = pack_bf2(v[2], v[3]);
    hi.z = pack_bf2(v[4], v[5]); hi.w = pack_bf2(v[6], v[7]);
    lo.x = pack_bf2(v[0] - bf_hi(v[0]), v[1] - bf_hi(v[1]));
    lo.y = pack_bf2(v[2] - bf_hi(v[2]), v[3] - bf_hi(v[3]));
    lo.z = pack_bf2(v[4] - bf_hi(v[4]), v[5] - bf_hi(v[5]));
    lo.w = pack_bf2(v[6] - bf_hi(v[6]), v[7] - bf_hi(v[7]));

    size_t base = ((size_t)(nb * 64 + kb) * 2) * 32 + lane;
    g_W2[base]      = hi;
    g_W2[base + 32] = lo;
}

// ---------------------------------------------------------------------------
// Split A = [x | h] into fragment-linear hi/lo bf16 tiles.
// ---------------------------------------------------------------------------
__global__ __launch_bounds__(256)
void split_a_kernel(const float* __restrict__ x, const float* __restrict__ h) {
    const int rb = blockIdx.x;
    const int tid = threadIdx.x;
    const int wid = tid >> 5;
    const int lane = tid & 31;

    const int r0 = lane >> 2;
    const int cq = (lane & 3) * 2;
    const size_t rowA = (size_t)rb * 16 + r0;
    const size_t rowB = rowA + 8;

#pragma unroll
    for (int j = 0; j < 8; j++) {
        int kb = wid * 8 + j;
        int kg = kb * 16 + cq;
        const float* srcA;
        const float* srcB;
        if (kb < 32) { srcA = x + rowA * I_DIM + kg;          srcB = x + rowB * I_DIM + kg; }
        else         { srcA = h + rowA * H_DIM + (kg - 512);  srcB = h + rowB * H_DIM + (kg - 512); }

        float a0 = srcA[0], a1 = srcA[1], a2 = srcA[8], a3 = srcA[9];
        float b0 = srcB[0], b1 = srcB[1], b2 = srcB[8], b3 = srcB[9];

        uint4 hi, lo;
        hi.x = pack_bf2(a0, a1); hi.y = pack_bf2(b0, b1);
        hi.z = pack_bf2(a2, a3); hi.w = pack_bf2(b2, b3);
        lo.x = pack_bf2(a0 - bf_hi(a0), a1 - bf_hi(a1));
        lo.y = pack_bf2(b0 - bf_hi(b0), b1 - bf_hi(b1));
        lo.z = pack_bf2(a2 - bf_hi(a2), a3 - bf_hi(a3));
        lo.w = pack_bf2(b2 - bf_hi(b2), b3 - bf_hi(b3));

        size_t base = ((size_t)(rb * 64 + kb) * 2) * 32 + lane;
        g_A2[base]      = hi;
        g_A2[base + 32] = lo;
    }
}

// ---------------------------------------------------------------------------
// GEMM: CTA tile 128x256, warp tile 64x64 (2x4 warps), BK=32, 4-stage cp.async.
// Stage layout (49152 B):
//   A: ((kb*2+term)*8 + mb)*512 + lane*16            (16 KB)
//   B: 16384 + ((kb*2+term)*16 + nb)*512 + lane*16   (32 KB)
// ---------------------------------------------------------------------------
#define STAGE_BYTES 49152
#define N_STAGES 4

__global__ __launch_bounds__(256)
void gemm_mma_kernel() {
    extern __shared__ char smem[];
    const uint32_t sbase = smem_u32(smem);

    const int tid  = threadIdx.x;
    const int wid  = tid >> 5;
    const int lane = tid & 31;
    const int bn = blockIdx.x;            // 0..3
    const int bm = blockIdx.y;            // 0..511
    const int wm = wid & 1;               // warp m (2)
    const int wn = wid >> 1;              // warp n (4)

    // cp.async mapping: 3072 chunks/stage, 12 per thread
    uint32_t soff[12];
    const uint4* gptr[12];
#pragma unroll
    for (int j = 0; j < 12; j++) {
        int c = tid + j * 256;
        if (c < 1024) {
            int cl   = c & 31;
            int mb   = (c >> 5) & 7;
            int term = (c >> 8) & 1;
            int kb   = (c >> 9) & 1;
            int rb = bm * 8 + mb;
            gptr[j] = g_A2 + (((size_t)(rb * 64 + kb) * 2 + term) * 32 + cl);
            soff[j] = (uint32_t)(c * 16);
        } else {
            int cb = c - 1024;
            int cl   = cb & 31;
            int nb   = (cb >> 5) & 15;
            int term = (cb >> 9) & 1;
            int kb   = (cb >> 10) & 1;
            int nbg = bn * 16 + nb;
            gptr[j] = g_W2 + (((size_t)(nbg * 64 + kb) * 2 + term) * 32 + cl);
            soff[j] = (uint32_t)(16384 + cb * 16);
        }
    }

    float acc[4][8][4];
#pragma unroll
    for (int a = 0; a < 4; a++)
#pragma unroll
        for (int b = 0; b < 8; b++)
#pragma unroll
            for (int d = 0; d < 4; d++) acc[a][b][d] = 0.f;

    // prologue: 3 stages
#pragma unroll
    for (int s = 0; s < 3; s++) {
#pragma unroll
        for (int j = 0; j < 12; j++)
            CP_ASYNC16(sbase + s * STAGE_BYTES + soff[j], gptr[j] + (size_t)s * 128);
        CP_COMMIT();
    }

    for (int i = 0; i < 32; i++) {
        CP_WAIT2();
        __syncthreads();

        if (i + 3 < 32) {
            uint32_t sbst = sbase + ((i + 3) & 3) * STAGE_BYTES;
#pragma unroll
            for (int j = 0; j < 12; j++)
                CP_ASYNC16(sbst + soff[j], gptr[j] + (size_t)(i + 3) * 128);
        }
        CP_COMMIT();

        const uint32_t st = sbase + (i & 3) * STAGE_BYTES;
#pragma unroll
        for (int kb = 0; kb < 2; kb++) {
            uint4 ah[4], al[4];
#pragma unroll
            for (int mt = 0; mt < 4; mt++) {
                int mb = wm * 4 + mt;
                LDS128(ah[mt], st + (uint32_t)(((kb * 2 + 0) * 8 + mb) * 512) + lane * 16);
                LDS128(al[mt], st + (uint32_t)(((kb * 2 + 1) * 8 + mb) * 512) + lane * 16);
            }
#pragma unroll
            for (int q = 0; q < 4; q++) {
                int nb = wn * 4 + q;
                uint4 bh, bl;
                LDS128(bh, st + (uint32_t)(16384 + ((kb * 2 + 0) * 16 + nb) * 512) + lane * 16);
                LDS128(bl, st + (uint32_t)(16384 + ((kb * 2 + 1) * 16 + nb) * 512) + lane * 16);
#pragma unroll
                for (int term = 0; term < 3; term++) {
#pragma unroll
                    for (int mt = 0; mt < 4; mt++) {
#pragma unroll
                        for (int p = 0; p < 2; p++) {
                            const uint4& A = (term == 2) ? al[mt] : ah[mt];
                            const uint4& B = (term == 1) ? bl : bh;
                            uint32_t b0 = p ? B.z : B.x;
                            uint32_t b1 = p ? B.w : B.y;
                            mma16816(acc[mt][q * 2 + p], A, b0, b1);
                        }
                    }
                }
            }
        }
        __syncthreads();
    }

    // store C
    const int g  = lane >> 2;
    const int tg = lane & 3;
#pragma unroll
    for (int mt = 0; mt < 4; mt++) {
        int row = bm * 128 + wm * 64 + mt * 16 + g;
#pragma unroll
        for (int nn = 0; nn < 8; nn++) {
            int col = bn * 256 + wn * 64 + nn * 8 + tg * 2;
            float2* p0 = (float2*)(g_C + (size_t)row * NTOT + col);
            float2* p1 = (float2*)(g_C + (size_t)(row + 8) * NTOT + col);
            *p0 = make_float2(acc[mt][nn][0], acc[mt][nn][1]);
            *p1 = make_float2(acc[mt][nn][2], acc[mt][nn][3]);
        }
    }
}

// ---------------------------------------------------------------------------
// Epilogue: 2 rows / 256-thread block, float4 vectorized (4 elems/thread).
// ---------------------------------------------------------------------------
__global__ __launch_bounds__(256)
void epilogue_kernel(const float* __restrict__ h,
                     const float* __restrict__ b_in, const float* __restrict__ b_tau,
                     const float* __restrict__ gamma, const float* __restrict__ beta,
                     float* __restrict__ out_h, float* __restrict__ out_tau) {
    const int tid = threadIdx.x;
    const int r   = tid >> 7;          // 0/1: which row in the block
    const int t   = tid & 127;         // float4 index within the row
    const size_t row = (size_t)blockIdx.x * 2 + r;

    float4 vt = *((const float4*)(g_C + row * NTOT) + t);
    float4 vf = *((const float4*)(g_C + row * NTOT + 512) + t);
    float4 vh = *((const float4*)(h + row * H_DIM) + t);
    float4 bt = ((const float4*)b_tau)[t];
    float4 bi = ((const float4*)b_in)[t];

    float y[4], tau[4];
    {
        const float* pt = &vt.x; const float* pf = &vf.x;
        const float* ph = &vh.x; const float* pbt = &bt.x; const float* pbi = &bi.x;
#pragma unroll
        for (int c = 0; c < 4; c++) {
            float sig = 1.0f / (1.0f + __expf(-(pt[c] + pbt[c])));
            tau[c] = 0.5f + 4.5f * sig;
            float f = tanhf(pf[c] + pbi[c]);
            y[c] = ph[c] + 0.1f * (f - ph[c]) / tau[c];
        }
    }

    float s = y[0] + y[1] + y[2] + y[3];
    float s2 = y[0]*y[0] + y[1]*y[1] + y[2]*y[2] + y[3]*y[3];

    __shared__ float2 red[8];
#pragma unroll
    for (int off = 16; off > 0; off >>= 1) {
        s  += __shfl_xor_sync(0xffffffffu, s, off);
        s2 += __shfl_xor_sync(0xffffffffu, s2, off);
    }
    int warp = tid >> 5;
    if ((tid & 31) == 0) red[warp] = make_float2(s, s2);
    __syncthreads();

    int wb = r * 4;
    float S  = red[wb].x + red[wb+1].x + red[wb+2].x + red[wb+3].x;
    float S2 = red[wb].y + red[wb+1].y + red[wb+2].y + red[wb+3].y;
    float mu  = S * (1.0f / H_DIM);
    float var = S2 * (1.0f / H_DIM) - mu * mu;
    float inv = rsqrtf(var + 1e-5f);

    float4 g4 = ((const float4*)gamma)[t];
    float4 be = ((const float4*)beta)[t];
    float4 oh, ot;
    oh.x = (y[0] - mu) * inv * g4.x + be.x;
    oh.y = (y[1] - mu) * inv * g4.y + be.y;
    oh.z = (y[2] - mu) * inv * g4.z + be.z;
    oh.w = (y[3] - mu) * inv * g4.w + be.w;
    ot.x = tau[0]; ot.y = tau[1]; ot.z = tau[2]; ot.w = tau[3];

    *((float4*)(out_h + row * H_DIM) + t) = oh;
    *((float4*)(out_tau + row * H_DIM) + t) = ot;
}

// ---------------------------------------------------------------------------
extern "C" void kernel_launch(void* const* d_in, const int* in_sizes, int n_in,
                              void* d_out, int out_size) {
    const float* x     = (const float*)d_in[0];
    const float* h     = (const float*)d_in[1];
    const float* W_in  = (const float*)d_in[2];
    const float* b_in  = (const float*)d_in[3];
    const float* W_rec = (const float*)d_in[4];
    const float* W_tau = (const float*)d_in[5];
    const float* b_tau = (const float*)d_in[6];
    const float* gamma = (const float*)d_in[7];
    const float* beta  = (const float*)d_in[8];

    const int B = in_sizes[0] / I_DIM;    // 65536

    float* out = (float*)d_out;
    float* out_h   = out;
    float* out_tau = out + (size_t)B * H_DIM;

    pack_w_kernel<<<512, 256>>>(W_in, W_rec, W_tau);
    split_a_kernel<<<B / 16, 256>>>(x, h);

    cudaFuncSetAttribute(gemm_mma_kernel,
                         cudaFuncAttributeMaxDynamicSharedMemorySize,
                         N_STAGES * STAGE_BYTES);
    dim3 ggrid(NTOT / 256, B / 128);      // (4, 512)
    gemm_mma_kernel<<<ggrid, 256, N_STAGES * STAGE_BYTES>>>();

    epilogue_kernel<<<B / 2, 256>>>(h, b_in, b_tau, gamma, beta, out_h, out_tau);
}